// round 12
// baseline (speedup 1.0000x reference)
#include <cuda_runtime.h>
#include <cuda_bf16.h>
#include <cstdint>
#include <cstddef>

// Problem constants
#define BB   512
#define AA   100
#define HH   1024
#define INN  77          // S*T = 7*11
#define KPAD 128         // padded input-feature dim
#define GG   4096        // 4*H
#define M1   (AA*BB)     // 51200
#define BH   (BB*HH)     // 524288

typedef __nv_bfloat16 bf16;

// ---------------- scratch (device globals; no allocation allowed) ----------------
__device__ bf16  g_xhi    [(size_t)M1 * KPAD];   // reordered+padded inputs hi
__device__ bf16  g_xlo    [(size_t)M1 * KPAD];
__device__ bf16  g_wembT_hi[(size_t)KPAD * HH];  // W_emb^T padded (for Wc GEMM)
__device__ bf16  g_wembT_lo[(size_t)KPAD * HH];
__device__ bf16  g_wc_hi  [(size_t)GG * KPAD];   // Wc = W_ih @ W_emb  [4096,128]
__device__ bf16  g_wc_lo  [(size_t)GG * KPAD];
__device__ float g_bias_c [GG];                  // W_ih@b_emb + b_ih + b_hh
__device__ float g_gx     [(size_t)M1 * GG];     // precomputed input gates
__device__ float g_gh     [(size_t)BB * GG];     // recurrent gates, current step
__device__ bf16  g_hhi    [BH];
__device__ bf16  g_hlo    [BH];
__device__ float g_c      [BH];
__device__ bf16  g_wih_hi [(size_t)GG * HH];
__device__ bf16  g_wih_lo [(size_t)GG * HH];
__device__ bf16  g_whh_hi [(size_t)GG * HH];
__device__ bf16  g_whh_lo [(size_t)GG * HH];

// ================= PTX helpers (sm_80+ standard; NO arch-'a' features) =========
__device__ __forceinline__ uint32_t smem_u32(const void* p) {
    uint32_t a;
    asm("{ .reg .u64 t; cvta.to.shared.u64 t, %1; cvt.u32.u64 %0, t; }" : "=r"(a) : "l"(p));
    return a;
}
#define SMEM_SWIZZLE_128B(o) ((o) ^ (((o) >> 3) & 0x70))

__device__ __forceinline__ void cp_async16(uint32_t smem_addr, const void* gptr) {
    asm volatile("cp.async.cg.shared.global [%0], [%1], 16;"
                 :: "r"(smem_addr), "l"(gptr) : "memory");
}
#define CP_COMMIT() asm volatile("cp.async.commit_group;" ::: "memory")
#define CP_WAIT(n)  asm volatile("cp.async.wait_group %0;" :: "n"(n) : "memory")

__device__ __forceinline__ void ldsm_x4(uint32_t addr, uint32_t& r0, uint32_t& r1,
                                        uint32_t& r2, uint32_t& r3) {
    asm volatile("ldmatrix.sync.aligned.m8n8.x4.shared.b16 {%0,%1,%2,%3}, [%4];"
                 : "=r"(r0), "=r"(r1), "=r"(r2), "=r"(r3) : "r"(addr));
}

__device__ __forceinline__ void mma_bf16(float* d, const uint32_t* a, const uint32_t* b) {
    asm volatile(
        "mma.sync.aligned.m16n8k16.row.col.f32.bf16.bf16.f32 "
        "{%0,%1,%2,%3}, {%4,%5,%6,%7}, {%8,%9}, {%0,%1,%2,%3};"
        : "+f"(d[0]), "+f"(d[1]), "+f"(d[2]), "+f"(d[3])
        : "r"(a[0]), "r"(a[1]), "r"(a[2]), "r"(a[3]), "r"(b[0]), "r"(b[1]));
}

__device__ __forceinline__ float fast_tanh(float x) {
    float y;
    asm("tanh.approx.f32 %0, %1;" : "=f"(y) : "f"(x));
    return y;
}
__device__ __forceinline__ float fast_sigmoid(float x) {
    return 1.f / (1.f + __expf(-x));
}

// ================= prep kernels =================
__global__ void reorder_pad_kernel(const float* __restrict__ inputs) {
    int idx = blockIdx.x * blockDim.x + threadIdx.x;
    if (idx >= M1 * KPAD) return;
    int i = idx & (KPAD - 1);
    int r = idx >> 7;         // r = a*B + b
    int b = r % BB;
    int a = r / BB;
    float v = (i < INN) ? inputs[(size_t)b * (AA * INN) + (size_t)a * INN + i] : 0.f;
    bf16 hb = __float2bfloat16(v);
    g_xhi[idx] = hb;
    g_xlo[idx] = __float2bfloat16(v - __bfloat162float(hb));
}

// W_emb [H,77] -> transposed+padded bf16 hi/lo [128, H]
__global__ void transpose_wemb_kernel(const float* __restrict__ W_emb) {
    int idx = blockIdx.x * blockDim.x + threadIdx.x;
    if (idx >= KPAD * HH) return;
    int h = idx & (HH - 1);
    int n = idx >> 10;        // padded input-feature index
    float v = (n < INN) ? W_emb[(size_t)h * INN + n] : 0.f;
    bf16 hb = __float2bfloat16(v);
    g_wembT_hi[idx] = hb;
    g_wembT_lo[idx] = __float2bfloat16(v - __bfloat162float(hb));
}

// bias_c[j] = dot(W_ih[j,:], b_emb) + b_ih[j] + b_hh[j]; one 128-thr block per j
__global__ void bias_c_kernel(const float* __restrict__ W_ih, const float* __restrict__ b_emb,
                              const float* __restrict__ b_ih, const float* __restrict__ b_hh) {
    __shared__ float red[4];
    const int j = blockIdx.x;
    const int tid = threadIdx.x;
    float s = 0.f;
    for (int h = tid; h < HH; h += 128)
        s += W_ih[(size_t)j * HH + h] * b_emb[h];
    #pragma unroll
    for (int o = 16; o > 0; o >>= 1) s += __shfl_down_sync(0xFFFFFFFFu, s, o);
    if ((tid & 31) == 0) red[tid >> 5] = s;
    __syncthreads();
    if (tid == 0)
        g_bias_c[j] = red[0] + red[1] + red[2] + red[3] + b_ih[j] + b_hh[j];
}

__global__ void state_init_kernel(const float* __restrict__ h0, const float* __restrict__ c0) {
    int i = blockIdx.x * blockDim.x + threadIdx.x;
    if (i >= BH) return;
    float h = h0[i];
    bf16 hb = __float2bfloat16(h);
    g_hhi[i] = hb;
    g_hlo[i] = __float2bfloat16(h - __bfloat162float(hb));
    g_c[i] = c0[i];
}

__global__ void decomp_bf16_kernel(const float* __restrict__ src, bf16* __restrict__ hi,
                                   bf16* __restrict__ lo, int n) {
    int i = blockIdx.x * blockDim.x + threadIdx.x;
    if (i >= n) return;
    float v = src[i];
    bf16 hb = __float2bfloat16(v);
    hi[i] = hb;
    lo[i] = __float2bfloat16(v - __bfloat162float(hb));
}

// ============== fused single-pass bf16-split GEMM, occupancy-tuned =============
// C[M,N] = (Ahi+Alo) @ (Bhi+Blo)^T (+bias); 3 MMA terms (AhBh, AhBl, AlBh).
// CTA tile 64x128, 4 warps (warp tile 64x32), K-chunk 32 with hi|lo interleaved
// per 128B smem row. 3-stage cp.async; 3 CTAs/SM.
// Loop order: wait -> ONE sync -> compute -> prefetch(ch+2) -> commit.
// (With 3 stages, prefetch target (ch+2)%3 never collides with any warp's
//  current read stage; per-chunk barrier count halves vs the old layout.)
// EPI: 0 = float C (+bias), 1 = bf16 hi/lo (+bias).
#define FCHUNK 32
#define A_TILE 8192                     // 64 rows * 128B
#define B_TILE 16384                    // 128 rows * 128B
#define F_STAGE (A_TILE + B_TILE)       // 24 KB
#define F_NSTAGE 3
#define SMEM_F_BYTES (F_NSTAGE * F_STAGE + 1024)

template<int EPI>
__global__ __launch_bounds__(128, 3)
void mma_gemm_f(const bf16* __restrict__ Ahi, const bf16* __restrict__ Alo,
                const bf16* __restrict__ Bhi, const bf16* __restrict__ Blo,
                const float* __restrict__ bias, float* __restrict__ C,
                bf16* __restrict__ Chi, bf16* __restrict__ Clo,
                int K, int ldc) {
    extern __shared__ char sm[];
    const uint32_t base = (smem_u32(sm) + 1023u) & ~1023u;
    const int tid = threadIdx.x;
    const int wid = tid >> 5, lane = tid & 31;
    const int wn = wid * 32;            // 4 warps across N; M=64 shared

    const bf16* Ahi_b = Ahi + (size_t)blockIdx.y * 64 * K;
    const bf16* Alo_b = Alo + (size_t)blockIdx.y * 64 * K;
    const bf16* Bhi_b = Bhi + (size_t)blockIdx.x * 128 * K;
    const bf16* Blo_b = Blo + (size_t)blockIdx.x * 128 * K;

    const int nchunk = K / FCHUNK;

    float acc[4][4][4];
    #pragma unroll
    for (int mi = 0; mi < 4; mi++)
        #pragma unroll
        for (int nj = 0; nj < 4; nj++)
            #pragma unroll
            for (int q = 0; q < 4; q++) acc[mi][nj][q] = 0.f;

    auto prefetch = [&](int ch) {
        const int kc = ch * FCHUNK;
        const uint32_t st = base + (uint32_t)(ch % F_NSTAGE) * F_STAGE;
        #pragma unroll
        for (int it = 0; it < 4; it++) {
            const int idx = it * 128 + tid;        // 0..511
            const int row = idx >> 3;
            const int g   = idx & 7;
            const uint32_t off = SMEM_SWIZZLE_128B((uint32_t)(row * 128 + g * 16));
            const bf16* src = (g < 4) ? (Ahi_b + (size_t)row * K + kc + g * 8)
                                      : (Alo_b + (size_t)row * K + kc + (g - 4) * 8);
            cp_async16(st + off, src);
        }
        #pragma unroll
        for (int it = 0; it < 8; it++) {
            const int idx = it * 128 + tid;        // 0..1023
            const int row = idx >> 3;
            const int g   = idx & 7;
            const uint32_t off = SMEM_SWIZZLE_128B((uint32_t)(row * 128 + g * 16));
            const bf16* src = (g < 4) ? (Bhi_b + (size_t)row * K + kc + g * 8)
                                      : (Blo_b + (size_t)row * K + kc + (g - 4) * 8);
            cp_async16(st + A_TILE + off, src);
        }
    };

    prefetch(0); CP_COMMIT();
    prefetch(1); CP_COMMIT();

    const int tsel = lane >> 3, rin = lane & 7;

    for (int ch = 0; ch < nchunk; ch++) {
        if (ch < nchunk - 1) { CP_WAIT(1); } else { CP_WAIT(0); }
        __syncthreads();

        const uint32_t st = base + (uint32_t)(ch % F_NSTAGE) * F_STAGE;
        const uint32_t sB = st + A_TILE;

        #pragma unroll
        for (int kk = 0; kk < FCHUNK; kk += 16) {
            const int colb = (kk + (tsel >> 1) * 8) * 2;   // hi byte col
            uint32_t ah[4][4], al[4][4];
            #pragma unroll
            for (int mi = 0; mi < 4; mi++) {
                const int row = mi * 16 + (tsel & 1) * 8 + rin;
                ldsm_x4(st + SMEM_SWIZZLE_128B((uint32_t)(row * 128 + colb)),
                        ah[mi][0], ah[mi][1], ah[mi][2], ah[mi][3]);
                ldsm_x4(st + SMEM_SWIZZLE_128B((uint32_t)(row * 128 + colb + 64)),
                        al[mi][0], al[mi][1], al[mi][2], al[mi][3]);
            }
            uint32_t bh[4][2], bl[4][2];
            #pragma unroll
            for (int g = 0; g < 2; g++) {
                const int row = wn + g * 16 + (tsel & 1) * 8 + rin;
                uint32_t r0, r1, r2, r3;
                ldsm_x4(sB + SMEM_SWIZZLE_128B((uint32_t)(row * 128 + colb)),
                        r0, r1, r2, r3);
                bh[g * 2 + 0][0] = r0; bh[g * 2 + 0][1] = r2;
                bh[g * 2 + 1][0] = r1; bh[g * 2 + 1][1] = r3;
                ldsm_x4(sB + SMEM_SWIZZLE_128B((uint32_t)(row * 128 + colb + 64)),
                        r0, r1, r2, r3);
                bl[g * 2 + 0][0] = r0; bl[g * 2 + 0][1] = r2;
                bl[g * 2 + 1][0] = r1; bl[g * 2 + 1][1] = r3;
            }
            #pragma unroll
            for (int mi = 0; mi < 4; mi++)
                #pragma unroll
                for (int nj = 0; nj < 4; nj++) {
                    mma_bf16(acc[mi][nj], ah[mi], bh[nj]);
                    mma_bf16(acc[mi][nj], ah[mi], bl[nj]);
                    mma_bf16(acc[mi][nj], al[mi], bh[nj]);
                }
        }

        if (ch + 2 < nchunk) {
            prefetch(ch + 2);
            CP_COMMIT();
        }
    }

    // ---------------- epilogue ----------------
    const int r0 = lane >> 2;
    const int c0 = (lane & 3) * 2;
    #pragma unroll
    for (int mi = 0; mi < 4; mi++) {
        const size_t m0 = (size_t)blockIdx.y * 64 + mi * 16;
        #pragma unroll
        for (int nj = 0; nj < 4; nj++) {
            const int n = blockIdx.x * 128 + wn + nj * 8 + c0;
            float bx = 0.f, by = 0.f;
            if (bias) { bx = bias[n]; by = bias[n + 1]; }
            float vs[4] = {acc[mi][nj][0] + bx, acc[mi][nj][1] + by,
                           acc[mi][nj][2] + bx, acc[mi][nj][3] + by};
            if (EPI == 0) {
                *(float2*)(C + (m0 + r0) * (size_t)ldc + n) = make_float2(vs[0], vs[1]);
                *(float2*)(C + (m0 + r0 + 8) * (size_t)ldc + n) = make_float2(vs[2], vs[3]);
            } else {
                #pragma unroll
                for (int rr = 0; rr < 2; rr++) {
                    const size_t mrow = m0 + r0 + rr * 8;
                    const float vx = vs[rr * 2], vy = vs[rr * 2 + 1];
                    const bf16 hx = __float2bfloat16(vx);
                    const bf16 hy = __float2bfloat16(vy);
                    Chi[mrow * (size_t)ldc + n]     = hx;
                    Chi[mrow * (size_t)ldc + n + 1] = hy;
                    Clo[mrow * (size_t)ldc + n]     = __float2bfloat16(vx - __bfloat162float(hx));
                    Clo[mrow * (size_t)ldc + n + 1] = __float2bfloat16(vy - __bfloat162float(hy));
                }
            }
        }
    }
}

// ---------------- LSTM cell elementwise (fast transcendentals) ----------------
__global__ void lstm_cell_kernel(const float* __restrict__ gx, float* __restrict__ out_t) {
    int idx = blockIdx.x * blockDim.x + threadIdx.x;
    if (idx >= BH) return;
    int b = idx / HH, hh = idx % HH;
    size_t base = (size_t)b * GG;
    float gi = gx[base + hh]          + g_gh[base + hh];
    float gf = gx[base + HH + hh]     + g_gh[base + HH + hh];
    float gg = gx[base + 2 * HH + hh] + g_gh[base + 2 * HH + hh];
    float go = gx[base + 3 * HH + hh] + g_gh[base + 3 * HH + hh];
    float i = fast_sigmoid(gi);
    float f = fast_sigmoid(gf);
    float g = fast_tanh(gg);
    float o = fast_sigmoid(go);
    float cn = f * g_c[idx] + i * g;
    float hn = o * fast_tanh(cn);
    g_c[idx] = cn;
    bf16 hb = __float2bfloat16(hn);
    g_hhi[idx] = hb;
    g_hlo[idx] = __float2bfloat16(hn - __bfloat162float(hb));
    out_t[idx] = hn;
}

__global__ void copy_hc_kernel(const float* __restrict__ last_h, float* __restrict__ dst) {
    int i = blockIdx.x * blockDim.x + threadIdx.x;
    if (i < BH) { dst[i] = last_h[i]; dst[BH + i] = g_c[i]; }
}

// ---------------- launch ----------------
extern "C" void kernel_launch(void* const* d_in, const int* in_sizes, int n_in,
                              void* d_out, int out_size) {
    const float* inputs = (const float*)d_in[0];
    const float* h0     = (const float*)d_in[1];
    const float* c0     = (const float*)d_in[2];
    const float* W_emb  = (const float*)d_in[3];
    const float* b_emb  = (const float*)d_in[4];
    const float* W_ih   = (const float*)d_in[5];
    const float* W_hh   = (const float*)d_in[6];
    const float* b_ih   = (const float*)d_in[7];
    const float* b_hh   = (const float*)d_in[8];
    float* out = (float*)d_out;

    // Real device addresses of scratch globals (host-shadow trap otherwise).
    float *p_gx, *p_gh, *p_biasc;
    bf16 *p_xhi, *p_xlo, *p_wTh, *p_wTl, *p_wch, *p_wcl, *p_hhi, *p_hlo;
    bf16 *p_wihh, *p_wihl, *p_whhh, *p_whhl;
    cudaGetSymbolAddress((void**)&p_xhi,  g_xhi);
    cudaGetSymbolAddress((void**)&p_xlo,  g_xlo);
    cudaGetSymbolAddress((void**)&p_wTh,  g_wembT_hi);
    cudaGetSymbolAddress((void**)&p_wTl,  g_wembT_lo);
    cudaGetSymbolAddress((void**)&p_wch,  g_wc_hi);
    cudaGetSymbolAddress((void**)&p_wcl,  g_wc_lo);
    cudaGetSymbolAddress((void**)&p_biasc,g_bias_c);
    cudaGetSymbolAddress((void**)&p_gx,   g_gx);
    cudaGetSymbolAddress((void**)&p_gh,   g_gh);
    cudaGetSymbolAddress((void**)&p_hhi,  g_hhi);
    cudaGetSymbolAddress((void**)&p_hlo,  g_hlo);
    cudaGetSymbolAddress((void**)&p_wihh, g_wih_hi);
    cudaGetSymbolAddress((void**)&p_wihl, g_wih_lo);
    cudaGetSymbolAddress((void**)&p_whhh, g_whh_hi);
    cudaGetSymbolAddress((void**)&p_whhl, g_whh_lo);

    cudaFuncSetAttribute(mma_gemm_f<0>,
                         cudaFuncAttributeMaxDynamicSharedMemorySize, SMEM_F_BYTES);
    cudaFuncSetAttribute(mma_gemm_f<1>,
                         cudaFuncAttributeMaxDynamicSharedMemorySize, SMEM_F_BYTES);

    // prep
    reorder_pad_kernel<<<(M1 * KPAD + 255) / 256, 256>>>(inputs);
    transpose_wemb_kernel<<<(KPAD * HH + 255) / 256, 256>>>(W_emb);
    state_init_kernel<<<(BH + 255) / 256, 256>>>(h0, c0);
    decomp_bf16_kernel<<<(GG * HH + 255) / 256, 256>>>(W_ih, p_wihh, p_wihl, GG * HH);
    decomp_bf16_kernel<<<(GG * HH + 255) / 256, 256>>>(W_hh, p_whhh, p_whhl, GG * HH);
    bias_c_kernel<<<GG, 128>>>(W_ih, b_emb, b_ih, b_hh);

    // Wc = W_ih @ W_emb -> bf16 hi/lo [4096,128]
    mma_gemm_f<1><<<dim3(KPAD / 128, GG / 64), 128, SMEM_F_BYTES>>>(
        p_wihh, p_wihl, p_wTh, p_wTl, nullptr, nullptr, p_wch, p_wcl, HH, KPAD);

    // gx = x @ Wc^T + bias_c : [51200,128] @ [4096,128]^T -> [51200,4096]
    mma_gemm_f<0><<<dim3(GG / 128, M1 / 64), 128, SMEM_F_BYTES>>>(
        p_xhi, p_xlo, p_wch, p_wcl, p_biasc, p_gx, nullptr, nullptr, KPAD, GG);

    // recurrence: GEMM + cell per step (R9-proven structure)
    for (int t = 0; t < AA; t++) {
        mma_gemm_f<0><<<dim3(GG / 128, BB / 64), 128, SMEM_F_BYTES>>>(
            p_hhi, p_hlo, p_whhh, p_whhl, nullptr, p_gh, nullptr, nullptr, HH, GG);
        lstm_cell_kernel<<<(BH + 255) / 256, 256>>>(
            p_gx + (size_t)t * BB * GG, out + (size_t)t * BH);
    }

    // final (h, c) after output — only if the harness buffer includes them
    if (out_size >= (AA + 2) * BH) {
        copy_hc_kernel<<<(BH + 255) / 256, 256>>>(out + (size_t)(AA - 1) * BH,
                                                  out + (size_t)AA * BH);
    }
}

// round 13
// speedup vs baseline: 1.3241x; 1.3241x over previous
#include <cuda_runtime.h>
#include <cuda_bf16.h>
#include <cuda_fp16.h>
#include <cstdint>
#include <cstddef>

// Problem constants
#define BB   512
#define AA   100
#define HH   1024
#define INN  77          // S*T = 7*11
#define KPAD 128         // padded input-feature dim
#define GG   4096        // 4*H
#define M1   (AA*BB)     // 51200
#define BH   (BB*HH)     // 524288

typedef __nv_bfloat16 bf16;

// ---------------- scratch (device globals; no allocation allowed) ----------------
__device__ bf16  g_xhi    [(size_t)M1 * KPAD];   // reordered+padded inputs hi
__device__ bf16  g_xlo    [(size_t)M1 * KPAD];
__device__ bf16  g_wembT_hi[(size_t)KPAD * HH];  // W_emb^T padded (for Wc GEMM)
__device__ bf16  g_wembT_lo[(size_t)KPAD * HH];
__device__ bf16  g_wc_hi  [(size_t)GG * KPAD];   // Wc = W_ih @ W_emb  [4096,128]
__device__ bf16  g_wc_lo  [(size_t)GG * KPAD];
__device__ float g_bias_c [GG];                  // W_ih@b_emb + b_ih + b_hh
__device__ float g_gx     [(size_t)M1 * GG];     // precomputed input gates
__device__ float g_gh     [(size_t)BB * GG];     // recurrent gates, current step
__device__ __half g_hf    [BH];                  // h state, single fp16
__device__ float g_c      [BH];
__device__ bf16  g_wih_hi [(size_t)GG * HH];
__device__ bf16  g_wih_lo [(size_t)GG * HH];
__device__ __half g_whh_hi[(size_t)GG * HH];     // Whh fp16 hi
__device__ __half g_whh_lo[(size_t)GG * HH];     // Whh fp16 lo (residual)

// ================= PTX helpers (sm_80+ standard; NO arch-'a' features) =========
__device__ __forceinline__ uint32_t smem_u32(const void* p) {
    uint32_t a;
    asm("{ .reg .u64 t; cvta.to.shared.u64 t, %1; cvt.u32.u64 %0, t; }" : "=r"(a) : "l"(p));
    return a;
}
#define SMEM_SWIZZLE_128B(o) ((o) ^ (((o) >> 3) & 0x70))

__device__ __forceinline__ void cp_async16(uint32_t smem_addr, const void* gptr) {
    asm volatile("cp.async.cg.shared.global [%0], [%1], 16;"
                 :: "r"(smem_addr), "l"(gptr) : "memory");
}
#define CP_COMMIT() asm volatile("cp.async.commit_group;" ::: "memory")
#define CP_WAIT(n)  asm volatile("cp.async.wait_group %0;" :: "n"(n) : "memory")

__device__ __forceinline__ void ldsm_x4(uint32_t addr, uint32_t& r0, uint32_t& r1,
                                        uint32_t& r2, uint32_t& r3) {
    asm volatile("ldmatrix.sync.aligned.m8n8.x4.shared.b16 {%0,%1,%2,%3}, [%4];"
                 : "=r"(r0), "=r"(r1), "=r"(r2), "=r"(r3) : "r"(addr));
}

__device__ __forceinline__ void mma_bf16(float* d, const uint32_t* a, const uint32_t* b) {
    asm volatile(
        "mma.sync.aligned.m16n8k16.row.col.f32.bf16.bf16.f32 "
        "{%0,%1,%2,%3}, {%4,%5,%6,%7}, {%8,%9}, {%0,%1,%2,%3};"
        : "+f"(d[0]), "+f"(d[1]), "+f"(d[2]), "+f"(d[3])
        : "r"(a[0]), "r"(a[1]), "r"(a[2]), "r"(a[3]), "r"(b[0]), "r"(b[1]));
}

__device__ __forceinline__ void mma_f16(float* d, const uint32_t* a, const uint32_t* b) {
    asm volatile(
        "mma.sync.aligned.m16n8k16.row.col.f32.f16.f16.f32 "
        "{%0,%1,%2,%3}, {%4,%5,%6,%7}, {%8,%9}, {%0,%1,%2,%3};"
        : "+f"(d[0]), "+f"(d[1]), "+f"(d[2]), "+f"(d[3])
        : "r"(a[0]), "r"(a[1]), "r"(a[2]), "r"(a[3]), "r"(b[0]), "r"(b[1]));
}

// ================= prep kernels =================
__global__ void reorder_pad_kernel(const float* __restrict__ inputs) {
    int idx = blockIdx.x * blockDim.x + threadIdx.x;
    if (idx >= M1 * KPAD) return;
    int i = idx & (KPAD - 1);
    int r = idx >> 7;         // r = a*B + b
    int b = r % BB;
    int a = r / BB;
    float v = (i < INN) ? inputs[(size_t)b * (AA * INN) + (size_t)a * INN + i] : 0.f;
    bf16 hb = __float2bfloat16(v);
    g_xhi[idx] = hb;
    g_xlo[idx] = __float2bfloat16(v - __bfloat162float(hb));
}

// W_emb [H,77] -> transposed+padded bf16 hi/lo [128, H]
__global__ void transpose_wemb_kernel(const float* __restrict__ W_emb) {
    int idx = blockIdx.x * blockDim.x + threadIdx.x;
    if (idx >= KPAD * HH) return;
    int h = idx & (HH - 1);
    int n = idx >> 10;        // padded input-feature index
    float v = (n < INN) ? W_emb[(size_t)h * INN + n] : 0.f;
    bf16 hb = __float2bfloat16(v);
    g_wembT_hi[idx] = hb;
    g_wembT_lo[idx] = __float2bfloat16(v - __bfloat162float(hb));
}

// bias_c[j] = dot(W_ih[j,:], b_emb) + b_ih[j] + b_hh[j]; one 128-thr block per j
__global__ void bias_c_kernel(const float* __restrict__ W_ih, const float* __restrict__ b_emb,
                              const float* __restrict__ b_ih, const float* __restrict__ b_hh) {
    __shared__ float red[4];
    const int j = blockIdx.x;
    const int tid = threadIdx.x;
    float s = 0.f;
    for (int h = tid; h < HH; h += 128)
        s += W_ih[(size_t)j * HH + h] * b_emb[h];
    #pragma unroll
    for (int o = 16; o > 0; o >>= 1) s += __shfl_down_sync(0xFFFFFFFFu, s, o);
    if ((tid & 31) == 0) red[tid >> 5] = s;
    __syncthreads();
    if (tid == 0)
        g_bias_c[j] = red[0] + red[1] + red[2] + red[3] + b_ih[j] + b_hh[j];
}

__global__ void state_init_kernel(const float* __restrict__ h0, const float* __restrict__ c0) {
    int i = blockIdx.x * blockDim.x + threadIdx.x;
    if (i >= BH) return;
    g_hf[i] = __float2half(h0[i]);
    g_c[i] = c0[i];
}

__global__ void decomp_bf16_kernel(const float* __restrict__ src, bf16* __restrict__ hi,
                                   bf16* __restrict__ lo, int n) {
    int i = blockIdx.x * blockDim.x + threadIdx.x;
    if (i >= n) return;
    float v = src[i];
    bf16 hb = __float2bfloat16(v);
    hi[i] = hb;
    lo[i] = __float2bfloat16(v - __bfloat162float(hb));
}

__global__ void decomp_f16_kernel(const float* __restrict__ src, __half* __restrict__ hi,
                                  __half* __restrict__ lo, int n) {
    int i = blockIdx.x * blockDim.x + threadIdx.x;
    if (i >= n) return;
    float v = src[i];
    __half hb = __float2half(v);
    hi[i] = hb;
    lo[i] = __float2half(v - __half2float(hb));
}

// ============== fused single-pass bf16-split GEMM (R9-proven, 3-term) ==========
// C[M,N] = (Ahi+Alo) @ (Bhi+Blo)^T (+bias); 3 MMA terms (AhBh, AhBl, AlBh).
// CTA tile 64x128, 4 warps (warp tile 64x32), K-chunk 32 with hi|lo interleaved
// per 128B smem row. 3-stage cp.async; 3 CTAs/SM.
// EPI: 0 = float C (+bias), 1 = bf16 hi/lo (+bias).
#define FCHUNK 32
#define A_TILE 8192                     // 64 rows * 128B
#define B_TILE 16384                    // 128 rows * 128B
#define F_STAGE (A_TILE + B_TILE)       // 24 KB
#define F_NSTAGE 3
#define SMEM_F_BYTES (F_NSTAGE * F_STAGE + 1024)

template<int EPI>
__global__ __launch_bounds__(128, 3)
void mma_gemm_f(const bf16* __restrict__ Ahi, const bf16* __restrict__ Alo,
                const bf16* __restrict__ Bhi, const bf16* __restrict__ Blo,
                const float* __restrict__ bias, float* __restrict__ C,
                bf16* __restrict__ Chi, bf16* __restrict__ Clo,
                int K, int ldc) {
    extern __shared__ char sm[];
    const uint32_t base = (smem_u32(sm) + 1023u) & ~1023u;
    const int tid = threadIdx.x;
    const int wid = tid >> 5, lane = tid & 31;
    const int wn = wid * 32;            // 4 warps across N; M=64 shared

    const bf16* Ahi_b = Ahi + (size_t)blockIdx.y * 64 * K;
    const bf16* Alo_b = Alo + (size_t)blockIdx.y * 64 * K;
    const bf16* Bhi_b = Bhi + (size_t)blockIdx.x * 128 * K;
    const bf16* Blo_b = Blo + (size_t)blockIdx.x * 128 * K;

    const int nchunk = K / FCHUNK;

    float acc[4][4][4];
    #pragma unroll
    for (int mi = 0; mi < 4; mi++)
        #pragma unroll
        for (int nj = 0; nj < 4; nj++)
            #pragma unroll
            for (int q = 0; q < 4; q++) acc[mi][nj][q] = 0.f;

    auto prefetch = [&](int ch) {
        const int kc = ch * FCHUNK;
        const uint32_t st = base + (uint32_t)(ch % F_NSTAGE) * F_STAGE;
        #pragma unroll
        for (int it = 0; it < 4; it++) {
            const int idx = it * 128 + tid;        // 0..511
            const int row = idx >> 3;
            const int g   = idx & 7;
            const uint32_t off = SMEM_SWIZZLE_128B((uint32_t)(row * 128 + g * 16));
            const bf16* src = (g < 4) ? (Ahi_b + (size_t)row * K + kc + g * 8)
                                      : (Alo_b + (size_t)row * K + kc + (g - 4) * 8);
            cp_async16(st + off, src);
        }
        #pragma unroll
        for (int it = 0; it < 8; it++) {
            const int idx = it * 128 + tid;        // 0..1023
            const int row = idx >> 3;
            const int g   = idx & 7;
            const uint32_t off = SMEM_SWIZZLE_128B((uint32_t)(row * 128 + g * 16));
            const bf16* src = (g < 4) ? (Bhi_b + (size_t)row * K + kc + g * 8)
                                      : (Blo_b + (size_t)row * K + kc + (g - 4) * 8);
            cp_async16(st + A_TILE + off, src);
        }
    };

    prefetch(0); CP_COMMIT();
    prefetch(1); CP_COMMIT();

    const int tsel = lane >> 3, rin = lane & 7;

    for (int ch = 0; ch < nchunk; ch++) {
        if (ch + 2 < nchunk) {
            prefetch(ch + 2);
            CP_COMMIT();
            CP_WAIT(2);
        } else {
            CP_WAIT(0);
        }
        __syncthreads();

        const uint32_t st = base + (uint32_t)(ch % F_NSTAGE) * F_STAGE;
        const uint32_t sB = st + A_TILE;

        #pragma unroll
        for (int kk = 0; kk < FCHUNK; kk += 16) {
            const int colb = (kk + (tsel >> 1) * 8) * 2;   // hi byte col
            uint32_t ah[4][4], al[4][4];
            #pragma unroll
            for (int mi = 0; mi < 4; mi++) {
                const int row = mi * 16 + (tsel & 1) * 8 + rin;
                ldsm_x4(st + SMEM_SWIZZLE_128B((uint32_t)(row * 128 + colb)),
                        ah[mi][0], ah[mi][1], ah[mi][2], ah[mi][3]);
                ldsm_x4(st + SMEM_SWIZZLE_128B((uint32_t)(row * 128 + colb + 64)),
                        al[mi][0], al[mi][1], al[mi][2], al[mi][3]);
            }
            uint32_t bh[4][2], bl[4][2];
            #pragma unroll
            for (int g = 0; g < 2; g++) {
                const int row = wn + g * 16 + (tsel & 1) * 8 + rin;
                uint32_t r0, r1, r2, r3;
                ldsm_x4(sB + SMEM_SWIZZLE_128B((uint32_t)(row * 128 + colb)),
                        r0, r1, r2, r3);
                bh[g * 2 + 0][0] = r0; bh[g * 2 + 0][1] = r2;
                bh[g * 2 + 1][0] = r1; bh[g * 2 + 1][1] = r3;
                ldsm_x4(sB + SMEM_SWIZZLE_128B((uint32_t)(row * 128 + colb + 64)),
                        r0, r1, r2, r3);
                bl[g * 2 + 0][0] = r0; bl[g * 2 + 0][1] = r2;
                bl[g * 2 + 1][0] = r1; bl[g * 2 + 1][1] = r3;
            }
            #pragma unroll
            for (int mi = 0; mi < 4; mi++)
                #pragma unroll
                for (int nj = 0; nj < 4; nj++) {
                    mma_bf16(acc[mi][nj], ah[mi], bh[nj]);
                    mma_bf16(acc[mi][nj], ah[mi], bl[nj]);
                    mma_bf16(acc[mi][nj], al[mi], bh[nj]);
                }
        }
        __syncthreads();
    }

    // ---------------- epilogue ----------------
    const int r0 = lane >> 2;
    const int c0 = (lane & 3) * 2;
    #pragma unroll
    for (int mi = 0; mi < 4; mi++) {
        const size_t m0 = (size_t)blockIdx.y * 64 + mi * 16;
        #pragma unroll
        for (int nj = 0; nj < 4; nj++) {
            const int n = blockIdx.x * 128 + wn + nj * 8 + c0;
            float bx = 0.f, by = 0.f;
            if (bias) { bx = bias[n]; by = bias[n + 1]; }
            float vs[4] = {acc[mi][nj][0] + bx, acc[mi][nj][1] + by,
                           acc[mi][nj][2] + bx, acc[mi][nj][3] + by};
            if (EPI == 0) {
                *(float2*)(C + (m0 + r0) * (size_t)ldc + n) = make_float2(vs[0], vs[1]);
                *(float2*)(C + (m0 + r0 + 8) * (size_t)ldc + n) = make_float2(vs[2], vs[3]);
            } else {
                #pragma unroll
                for (int rr = 0; rr < 2; rr++) {
                    const size_t mrow = m0 + r0 + rr * 8;
                    const float vx = vs[rr * 2], vy = vs[rr * 2 + 1];
                    const bf16 hx = __float2bfloat16(vx);
                    const bf16 hy = __float2bfloat16(vy);
                    Chi[mrow * (size_t)ldc + n]     = hx;
                    Chi[mrow * (size_t)ldc + n + 1] = hy;
                    Clo[mrow * (size_t)ldc + n]     = __float2bfloat16(vx - __bfloat162float(hx));
                    Clo[mrow * (size_t)ldc + n + 1] = __float2bfloat16(vy - __bfloat162float(hy));
                }
            }
        }
    }
}

// ============== recurrence GEMM: fp16, 2-term (A single, B hi+lo) ==============
// gh[B,4H] = fp16(h) @ (Whh_hi + Whh_lo)^T. A tile rows use only bytes [0,64)
// of each 128B smem row (lo half never loaded/read). B rows: [hi 64B | lo 64B].
// Same 3-stage pipeline, 3 CTAs/SM, grid (32, 8).
__global__ __launch_bounds__(128, 3)
void mma_gemm_h(const __half* __restrict__ A,
                const __half* __restrict__ Bhi, const __half* __restrict__ Blo,
                float* __restrict__ C, int K, int ldc) {
    extern __shared__ char sm[];
    const uint32_t base = (smem_u32(sm) + 1023u) & ~1023u;
    const int tid = threadIdx.x;
    const int wid = tid >> 5, lane = tid & 31;
    const int wn = wid * 32;

    const __half* A_b   = A   + (size_t)blockIdx.y * 64 * K;
    const __half* Bhi_b = Bhi + (size_t)blockIdx.x * 128 * K;
    const __half* Blo_b = Blo + (size_t)blockIdx.x * 128 * K;

    const int nchunk = K / FCHUNK;

    float acc[4][4][4];
    #pragma unroll
    for (int mi = 0; mi < 4; mi++)
        #pragma unroll
        for (int nj = 0; nj < 4; nj++)
            #pragma unroll
            for (int q = 0; q < 4; q++) acc[mi][nj][q] = 0.f;

    auto prefetch = [&](int ch) {
        const int kc = ch * FCHUNK;
        const uint32_t st = base + (uint32_t)(ch % F_NSTAGE) * F_STAGE;
        // A: 64 rows x 4 x 16B groups (hi half of each 128B row only)
        #pragma unroll
        for (int it = 0; it < 2; it++) {
            const int idx = it * 128 + tid;        // 0..255
            const int row = idx >> 2;
            const int g   = idx & 3;
            const uint32_t off = SMEM_SWIZZLE_128B((uint32_t)(row * 128 + g * 16));
            cp_async16(st + off, A_b + (size_t)row * K + kc + g * 8);
        }
        // B: 128 rows x 8 groups (hi | lo)
        #pragma unroll
        for (int it = 0; it < 8; it++) {
            const int idx = it * 128 + tid;        // 0..1023
            const int row = idx >> 3;
            const int g   = idx & 7;
            const uint32_t off = SMEM_SWIZZLE_128B((uint32_t)(row * 128 + g * 16));
            const __half* src = (g < 4) ? (Bhi_b + (size_t)row * K + kc + g * 8)
                                        : (Blo_b + (size_t)row * K + kc + (g - 4) * 8);
            cp_async16(st + A_TILE + off, src);
        }
    };

    prefetch(0); CP_COMMIT();
    prefetch(1); CP_COMMIT();

    const int tsel = lane >> 3, rin = lane & 7;

    for (int ch = 0; ch < nchunk; ch++) {
        if (ch + 2 < nchunk) {
            prefetch(ch + 2);
            CP_COMMIT();
            CP_WAIT(2);
        } else {
            CP_WAIT(0);
        }
        __syncthreads();

        const uint32_t st = base + (uint32_t)(ch % F_NSTAGE) * F_STAGE;
        const uint32_t sB = st + A_TILE;

        #pragma unroll
        for (int kk = 0; kk < FCHUNK; kk += 16) {
            const int colb = (kk + (tsel >> 1) * 8) * 2;
            uint32_t ah[4][4];
            #pragma unroll
            for (int mi = 0; mi < 4; mi++) {
                const int row = mi * 16 + (tsel & 1) * 8 + rin;
                ldsm_x4(st + SMEM_SWIZZLE_128B((uint32_t)(row * 128 + colb)),
                        ah[mi][0], ah[mi][1], ah[mi][2], ah[mi][3]);
            }
            uint32_t bh[4][2], bl[4][2];
            #pragma unroll
            for (int g = 0; g < 2; g++) {
                const int row = wn + g * 16 + (tsel & 1) * 8 + rin;
                uint32_t r0, r1, r2, r3;
                ldsm_x4(sB + SMEM_SWIZZLE_128B((uint32_t)(row * 128 + colb)),
                        r0, r1, r2, r3);
                bh[g * 2 + 0][0] = r0; bh[g * 2 + 0][1] = r2;
                bh[g * 2 + 1][0] = r1; bh[g * 2 + 1][1] = r3;
                ldsm_x4(sB + SMEM_SWIZZLE_128B((uint32_t)(row * 128 + colb + 64)),
                        r0, r1, r2, r3);
                bl[g * 2 + 0][0] = r0; bl[g * 2 + 0][1] = r2;
                bl[g * 2 + 1][0] = r1; bl[g * 2 + 1][1] = r3;
            }
            #pragma unroll
            for (int mi = 0; mi < 4; mi++)
                #pragma unroll
                for (int nj = 0; nj < 4; nj++) {
                    mma_f16(acc[mi][nj], ah[mi], bh[nj]);
                    mma_f16(acc[mi][nj], ah[mi], bl[nj]);
                }
        }
        __syncthreads();
    }

    // epilogue (no bias, float C)
    const int r0 = lane >> 2;
    const int c0 = (lane & 3) * 2;
    #pragma unroll
    for (int mi = 0; mi < 4; mi++) {
        const size_t m0 = (size_t)blockIdx.y * 64 + mi * 16;
        #pragma unroll
        for (int nj = 0; nj < 4; nj++) {
            const int n = blockIdx.x * 128 + wn + nj * 8 + c0;
            *(float2*)(C + (m0 + r0) * (size_t)ldc + n) =
                make_float2(acc[mi][nj][0], acc[mi][nj][1]);
            *(float2*)(C + (m0 + r0 + 8) * (size_t)ldc + n) =
                make_float2(acc[mi][nj][2], acc[mi][nj][3]);
        }
    }
}

// ---------------- LSTM cell elementwise (libm; h -> single fp16) ----------------
__global__ void lstm_cell_kernel(const float* __restrict__ gx, float* __restrict__ out_t) {
    int idx = blockIdx.x * blockDim.x + threadIdx.x;
    if (idx >= BH) return;
    int b = idx / HH, hh = idx % HH;
    size_t base = (size_t)b * GG;
    float gi = gx[base + hh]          + g_gh[base + hh];
    float gf = gx[base + HH + hh]     + g_gh[base + HH + hh];
    float gg = gx[base + 2 * HH + hh] + g_gh[base + 2 * HH + hh];
    float go = gx[base + 3 * HH + hh] + g_gh[base + 3 * HH + hh];
    float i = 1.f / (1.f + expf(-gi));
    float f = 1.f / (1.f + expf(-gf));
    float g = tanhf(gg);
    float o = 1.f / (1.f + expf(-go));
    float cn = f * g_c[idx] + i * g;
    float hn = o * tanhf(cn);
    g_c[idx] = cn;
    g_hf[idx] = __float2half(hn);
    out_t[idx] = hn;
}

__global__ void copy_hc_kernel(const float* __restrict__ last_h, float* __restrict__ dst) {
    int i = blockIdx.x * blockDim.x + threadIdx.x;
    if (i < BH) { dst[i] = last_h[i]; dst[BH + i] = g_c[i]; }
}

// ---------------- launch ----------------
extern "C" void kernel_launch(void* const* d_in, const int* in_sizes, int n_in,
                              void* d_out, int out_size) {
    const float* inputs = (const float*)d_in[0];
    const float* h0     = (const float*)d_in[1];
    const float* c0     = (const float*)d_in[2];
    const float* W_emb  = (const float*)d_in[3];
    const float* b_emb  = (const float*)d_in[4];
    const float* W_ih   = (const float*)d_in[5];
    const float* W_hh   = (const float*)d_in[6];
    const float* b_ih   = (const float*)d_in[7];
    const float* b_hh   = (const float*)d_in[8];
    float* out = (float*)d_out;

    // Real device addresses of scratch globals (host-shadow trap otherwise).
    float *p_gx, *p_gh, *p_biasc;
    bf16 *p_xhi, *p_xlo, *p_wTh, *p_wTl, *p_wch, *p_wcl;
    bf16 *p_wihh, *p_wihl;
    __half *p_hf, *p_whhh, *p_whhl;
    cudaGetSymbolAddress((void**)&p_xhi,  g_xhi);
    cudaGetSymbolAddress((void**)&p_xlo,  g_xlo);
    cudaGetSymbolAddress((void**)&p_wTh,  g_wembT_hi);
    cudaGetSymbolAddress((void**)&p_wTl,  g_wembT_lo);
    cudaGetSymbolAddress((void**)&p_wch,  g_wc_hi);
    cudaGetSymbolAddress((void**)&p_wcl,  g_wc_lo);
    cudaGetSymbolAddress((void**)&p_biasc,g_bias_c);
    cudaGetSymbolAddress((void**)&p_gx,   g_gx);
    cudaGetSymbolAddress((void**)&p_gh,   g_gh);
    cudaGetSymbolAddress((void**)&p_hf,   g_hf);
    cudaGetSymbolAddress((void**)&p_wihh, g_wih_hi);
    cudaGetSymbolAddress((void**)&p_wihl, g_wih_lo);
    cudaGetSymbolAddress((void**)&p_whhh, g_whh_hi);
    cudaGetSymbolAddress((void**)&p_whhl, g_whh_lo);

    cudaFuncSetAttribute(mma_gemm_f<0>,
                         cudaFuncAttributeMaxDynamicSharedMemorySize, SMEM_F_BYTES);
    cudaFuncSetAttribute(mma_gemm_f<1>,
                         cudaFuncAttributeMaxDynamicSharedMemorySize, SMEM_F_BYTES);
    cudaFuncSetAttribute(mma_gemm_h,
                         cudaFuncAttributeMaxDynamicSharedMemorySize, SMEM_F_BYTES);

    // prep
    reorder_pad_kernel<<<(M1 * KPAD + 255) / 256, 256>>>(inputs);
    transpose_wemb_kernel<<<(KPAD * HH + 255) / 256, 256>>>(W_emb);
    state_init_kernel<<<(BH + 255) / 256, 256>>>(h0, c0);
    decomp_bf16_kernel<<<(GG * HH + 255) / 256, 256>>>(W_ih, p_wihh, p_wihl, GG * HH);
    decomp_f16_kernel<<<(GG * HH + 255) / 256, 256>>>(W_hh, p_whhh, p_whhl, GG * HH);
    bias_c_kernel<<<GG, 128>>>(W_ih, b_emb, b_ih, b_hh);

    // Wc = W_ih @ W_emb -> bf16 hi/lo [4096,128]
    mma_gemm_f<1><<<dim3(KPAD / 128, GG / 64), 128, SMEM_F_BYTES>>>(
        p_wihh, p_wihl, p_wTh, p_wTl, nullptr, nullptr, p_wch, p_wcl, HH, KPAD);

    // gx = x @ Wc^T + bias_c : [51200,128] @ [4096,128]^T -> [51200,4096]
    mma_gemm_f<0><<<dim3(GG / 128, M1 / 64), 128, SMEM_F_BYTES>>>(
        p_xhi, p_xlo, p_wch, p_wcl, p_biasc, p_gx, nullptr, nullptr, KPAD, GG);

    // recurrence: fp16 2-term GEMM + cell per step
    for (int t = 0; t < AA; t++) {
        mma_gemm_h<<<dim3(GG / 128, BB / 64), 128, SMEM_F_BYTES>>>(
            p_hf, p_whhh, p_whhl, p_gh, HH, GG);
        lstm_cell_kernel<<<(BH + 255) / 256, 256>>>(
            p_gx + (size_t)t * BB * GG, out + (size_t)t * BH);
    }

    // final (h, c) after output — only if the harness buffer includes them
    if (out_size >= (AA + 2) * BH) {
        copy_hc_kernel<<<(BH + 255) / 256, 256>>>(out + (size_t)(AA - 1) * BH,
                                                  out + (size_t)AA * BH);
    }
}

// round 14
// speedup vs baseline: 2.0397x; 1.5404x over previous
#include <cuda_runtime.h>
#include <cuda_bf16.h>
#include <cuda_fp16.h>
#include <cstdint>
#include <cstddef>

// Problem constants
#define BB   512
#define AA   100
#define HH   1024
#define INN  77          // S*T = 7*11
#define KPAD 128         // padded input-feature dim
#define GG   4096        // 4*H
#define M1   (AA*BB)     // 51200
#define BH   (BB*HH)     // 524288

typedef __nv_bfloat16 bf16;

// ---------------- scratch (device globals; no allocation allowed) ----------------
__device__ bf16  g_xhi    [(size_t)M1 * KPAD];   // reordered+padded inputs hi
__device__ bf16  g_xlo    [(size_t)M1 * KPAD];
__device__ bf16  g_wembT_hi[(size_t)KPAD * HH];  // W_emb^T padded (for Wc GEMM)
__device__ bf16  g_wembT_lo[(size_t)KPAD * HH];
__device__ bf16  g_wc_hi  [(size_t)GG * KPAD];   // Wc = W_ih @ W_emb  [4096,128]
__device__ bf16  g_wc_lo  [(size_t)GG * KPAD];
__device__ float g_bias_c [GG];                  // W_ih@b_emb + b_ih + b_hh
__device__ float g_gx     [(size_t)M1 * GG];     // precomputed input gates
__device__ float g_gh     [(size_t)BB * GG];     // recurrent gates, current step
__device__ __half g_hf    [BH];                  // h state, single fp16
__device__ float g_c      [BH];
__device__ bf16  g_wih_hi [(size_t)GG * HH];
__device__ bf16  g_wih_lo [(size_t)GG * HH];
__device__ __half g_whh   [(size_t)GG * HH];     // Whh single fp16

// ================= PTX helpers (sm_80+ standard; NO arch-'a' features) =========
__device__ __forceinline__ uint32_t smem_u32(const void* p) {
    uint32_t a;
    asm("{ .reg .u64 t; cvta.to.shared.u64 t, %1; cvt.u32.u64 %0, t; }" : "=r"(a) : "l"(p));
    return a;
}
#define SMEM_SWIZZLE_128B(o) ((o) ^ (((o) >> 3) & 0x70))

__device__ __forceinline__ void cp_async16(uint32_t smem_addr, const void* gptr) {
    asm volatile("cp.async.cg.shared.global [%0], [%1], 16;"
                 :: "r"(smem_addr), "l"(gptr) : "memory");
}
#define CP_COMMIT() asm volatile("cp.async.commit_group;" ::: "memory")
#define CP_WAIT(n)  asm volatile("cp.async.wait_group %0;" :: "n"(n) : "memory")

__device__ __forceinline__ void ldsm_x4(uint32_t addr, uint32_t& r0, uint32_t& r1,
                                        uint32_t& r2, uint32_t& r3) {
    asm volatile("ldmatrix.sync.aligned.m8n8.x4.shared.b16 {%0,%1,%2,%3}, [%4];"
                 : "=r"(r0), "=r"(r1), "=r"(r2), "=r"(r3) : "r"(addr));
}

__device__ __forceinline__ void mma_bf16(float* d, const uint32_t* a, const uint32_t* b) {
    asm volatile(
        "mma.sync.aligned.m16n8k16.row.col.f32.bf16.bf16.f32 "
        "{%0,%1,%2,%3}, {%4,%5,%6,%7}, {%8,%9}, {%0,%1,%2,%3};"
        : "+f"(d[0]), "+f"(d[1]), "+f"(d[2]), "+f"(d[3])
        : "r"(a[0]), "r"(a[1]), "r"(a[2]), "r"(a[3]), "r"(b[0]), "r"(b[1]));
}

__device__ __forceinline__ void mma_f16(float* d, const uint32_t* a, const uint32_t* b) {
    asm volatile(
        "mma.sync.aligned.m16n8k16.row.col.f32.f16.f16.f32 "
        "{%0,%1,%2,%3}, {%4,%5,%6,%7}, {%8,%9}, {%0,%1,%2,%3};"
        : "+f"(d[0]), "+f"(d[1]), "+f"(d[2]), "+f"(d[3])
        : "r"(a[0]), "r"(a[1]), "r"(a[2]), "r"(a[3]), "r"(b[0]), "r"(b[1]));
}

// ================= prep kernels =================
__global__ void reorder_pad_kernel(const float* __restrict__ inputs) {
    int idx = blockIdx.x * blockDim.x + threadIdx.x;
    if (idx >= M1 * KPAD) return;
    int i = idx & (KPAD - 1);
    int r = idx >> 7;         // r = a*B + b
    int b = r % BB;
    int a = r / BB;
    float v = (i < INN) ? inputs[(size_t)b * (AA * INN) + (size_t)a * INN + i] : 0.f;
    bf16 hb = __float2bfloat16(v);
    g_xhi[idx] = hb;
    g_xlo[idx] = __float2bfloat16(v - __bfloat162float(hb));
}

// W_emb [H,77] -> transposed+padded bf16 hi/lo [128, H]
__global__ void transpose_wemb_kernel(const float* __restrict__ W_emb) {
    int idx = blockIdx.x * blockDim.x + threadIdx.x;
    if (idx >= KPAD * HH) return;
    int h = idx & (HH - 1);
    int n = idx >> 10;        // padded input-feature index
    float v = (n < INN) ? W_emb[(size_t)h * INN + n] : 0.f;
    bf16 hb = __float2bfloat16(v);
    g_wembT_hi[idx] = hb;
    g_wembT_lo[idx] = __float2bfloat16(v - __bfloat162float(hb));
}

// bias_c[j] = dot(W_ih[j,:], b_emb) + b_ih[j] + b_hh[j]; one 128-thr block per j
__global__ void bias_c_kernel(const float* __restrict__ W_ih, const float* __restrict__ b_emb,
                              const float* __restrict__ b_ih, const float* __restrict__ b_hh) {
    __shared__ float red[4];
    const int j = blockIdx.x;
    const int tid = threadIdx.x;
    float s = 0.f;
    for (int h = tid; h < HH; h += 128)
        s += W_ih[(size_t)j * HH + h] * b_emb[h];
    #pragma unroll
    for (int o = 16; o > 0; o >>= 1) s += __shfl_down_sync(0xFFFFFFFFu, s, o);
    if ((tid & 31) == 0) red[tid >> 5] = s;
    __syncthreads();
    if (tid == 0)
        g_bias_c[j] = red[0] + red[1] + red[2] + red[3] + b_ih[j] + b_hh[j];
}

__global__ void state_init_kernel(const float* __restrict__ h0, const float* __restrict__ c0) {
    int i = blockIdx.x * blockDim.x + threadIdx.x;
    if (i >= BH) return;
    g_hf[i] = __float2half(h0[i]);
    g_c[i] = c0[i];
}

__global__ void decomp_bf16_kernel(const float* __restrict__ src, bf16* __restrict__ hi,
                                   bf16* __restrict__ lo, int n) {
    int i = blockIdx.x * blockDim.x + threadIdx.x;
    if (i >= n) return;
    float v = src[i];
    bf16 hb = __float2bfloat16(v);
    hi[i] = hb;
    lo[i] = __float2bfloat16(v - __bfloat162float(hb));
}

__global__ void conv_f16_kernel(const float* __restrict__ src, __half* __restrict__ dst, int n) {
    int i = blockIdx.x * blockDim.x + threadIdx.x;
    if (i < n) dst[i] = __float2half(src[i]);
}

// ============== fused single-pass bf16-split GEMM (R9-proven, 3-term) ==========
// C[M,N] = (Ahi+Alo) @ (Bhi+Blo)^T (+bias); 3 MMA terms (AhBh, AhBl, AlBh).
// CTA tile 64x128, 4 warps (warp tile 64x32), K-chunk 32 with hi|lo interleaved
// per 128B smem row. 3-stage cp.async; 3 CTAs/SM.
// EPI: 0 = float C (+bias), 1 = bf16 hi/lo (+bias).
#define FCHUNK 32
#define A_TILE 8192                     // 64 rows * 128B
#define B_TILE 16384                    // 128 rows * 128B
#define F_STAGE (A_TILE + B_TILE)       // 24 KB
#define F_NSTAGE 3
#define SMEM_F_BYTES (F_NSTAGE * F_STAGE + 1024)

template<int EPI>
__global__ __launch_bounds__(128, 3)
void mma_gemm_f(const bf16* __restrict__ Ahi, const bf16* __restrict__ Alo,
                const bf16* __restrict__ Bhi, const bf16* __restrict__ Blo,
                const float* __restrict__ bias, float* __restrict__ C,
                bf16* __restrict__ Chi, bf16* __restrict__ Clo,
                int K, int ldc) {
    extern __shared__ char sm[];
    const uint32_t base = (smem_u32(sm) + 1023u) & ~1023u;
    const int tid = threadIdx.x;
    const int wid = tid >> 5, lane = tid & 31;
    const int wn = wid * 32;            // 4 warps across N; M=64 shared

    const bf16* Ahi_b = Ahi + (size_t)blockIdx.y * 64 * K;
    const bf16* Alo_b = Alo + (size_t)blockIdx.y * 64 * K;
    const bf16* Bhi_b = Bhi + (size_t)blockIdx.x * 128 * K;
    const bf16* Blo_b = Blo + (size_t)blockIdx.x * 128 * K;

    const int nchunk = K / FCHUNK;

    float acc[4][4][4];
    #pragma unroll
    for (int mi = 0; mi < 4; mi++)
        #pragma unroll
        for (int nj = 0; nj < 4; nj++)
            #pragma unroll
            for (int q = 0; q < 4; q++) acc[mi][nj][q] = 0.f;

    auto prefetch = [&](int ch) {
        const int kc = ch * FCHUNK;
        const uint32_t st = base + (uint32_t)(ch % F_NSTAGE) * F_STAGE;
        #pragma unroll
        for (int it = 0; it < 4; it++) {
            const int idx = it * 128 + tid;        // 0..511
            const int row = idx >> 3;
            const int g   = idx & 7;
            const uint32_t off = SMEM_SWIZZLE_128B((uint32_t)(row * 128 + g * 16));
            const bf16* src = (g < 4) ? (Ahi_b + (size_t)row * K + kc + g * 8)
                                      : (Alo_b + (size_t)row * K + kc + (g - 4) * 8);
            cp_async16(st + off, src);
        }
        #pragma unroll
        for (int it = 0; it < 8; it++) {
            const int idx = it * 128 + tid;        // 0..1023
            const int row = idx >> 3;
            const int g   = idx & 7;
            const uint32_t off = SMEM_SWIZZLE_128B((uint32_t)(row * 128 + g * 16));
            const bf16* src = (g < 4) ? (Bhi_b + (size_t)row * K + kc + g * 8)
                                      : (Blo_b + (size_t)row * K + kc + (g - 4) * 8);
            cp_async16(st + A_TILE + off, src);
        }
    };

    prefetch(0); CP_COMMIT();
    prefetch(1); CP_COMMIT();

    const int tsel = lane >> 3, rin = lane & 7;

    for (int ch = 0; ch < nchunk; ch++) {
        if (ch + 2 < nchunk) {
            prefetch(ch + 2);
            CP_COMMIT();
            CP_WAIT(2);
        } else {
            CP_WAIT(0);
        }
        __syncthreads();

        const uint32_t st = base + (uint32_t)(ch % F_NSTAGE) * F_STAGE;
        const uint32_t sB = st + A_TILE;

        #pragma unroll
        for (int kk = 0; kk < FCHUNK; kk += 16) {
            const int colb = (kk + (tsel >> 1) * 8) * 2;   // hi byte col
            uint32_t ah[4][4], al[4][4];
            #pragma unroll
            for (int mi = 0; mi < 4; mi++) {
                const int row = mi * 16 + (tsel & 1) * 8 + rin;
                ldsm_x4(st + SMEM_SWIZZLE_128B((uint32_t)(row * 128 + colb)),
                        ah[mi][0], ah[mi][1], ah[mi][2], ah[mi][3]);
                ldsm_x4(st + SMEM_SWIZZLE_128B((uint32_t)(row * 128 + colb + 64)),
                        al[mi][0], al[mi][1], al[mi][2], al[mi][3]);
            }
            uint32_t bh[4][2], bl[4][2];
            #pragma unroll
            for (int g = 0; g < 2; g++) {
                const int row = wn + g * 16 + (tsel & 1) * 8 + rin;
                uint32_t r0, r1, r2, r3;
                ldsm_x4(sB + SMEM_SWIZZLE_128B((uint32_t)(row * 128 + colb)),
                        r0, r1, r2, r3);
                bh[g * 2 + 0][0] = r0; bh[g * 2 + 0][1] = r2;
                bh[g * 2 + 1][0] = r1; bh[g * 2 + 1][1] = r3;
                ldsm_x4(sB + SMEM_SWIZZLE_128B((uint32_t)(row * 128 + colb + 64)),
                        r0, r1, r2, r3);
                bl[g * 2 + 0][0] = r0; bl[g * 2 + 0][1] = r2;
                bl[g * 2 + 1][0] = r1; bl[g * 2 + 1][1] = r3;
            }
            #pragma unroll
            for (int mi = 0; mi < 4; mi++)
                #pragma unroll
                for (int nj = 0; nj < 4; nj++) {
                    mma_bf16(acc[mi][nj], ah[mi], bh[nj]);
                    mma_bf16(acc[mi][nj], ah[mi], bl[nj]);
                    mma_bf16(acc[mi][nj], al[mi], bh[nj]);
                }
        }
        __syncthreads();
    }

    // ---------------- epilogue ----------------
    const int r0 = lane >> 2;
    const int c0 = (lane & 3) * 2;
    #pragma unroll
    for (int mi = 0; mi < 4; mi++) {
        const size_t m0 = (size_t)blockIdx.y * 64 + mi * 16;
        #pragma unroll
        for (int nj = 0; nj < 4; nj++) {
            const int n = blockIdx.x * 128 + wn + nj * 8 + c0;
            float bx = 0.f, by = 0.f;
            if (bias) { bx = bias[n]; by = bias[n + 1]; }
            float vs[4] = {acc[mi][nj][0] + bx, acc[mi][nj][1] + by,
                           acc[mi][nj][2] + bx, acc[mi][nj][3] + by};
            if (EPI == 0) {
                *(float2*)(C + (m0 + r0) * (size_t)ldc + n) = make_float2(vs[0], vs[1]);
                *(float2*)(C + (m0 + r0 + 8) * (size_t)ldc + n) = make_float2(vs[2], vs[3]);
            } else {
                #pragma unroll
                for (int rr = 0; rr < 2; rr++) {
                    const size_t mrow = m0 + r0 + rr * 8;
                    const float vx = vs[rr * 2], vy = vs[rr * 2 + 1];
                    const bf16 hx = __float2bfloat16(vx);
                    const bf16 hy = __float2bfloat16(vy);
                    Chi[mrow * (size_t)ldc + n]     = hx;
                    Chi[mrow * (size_t)ldc + n + 1] = hy;
                    Clo[mrow * (size_t)ldc + n]     = __float2bfloat16(vx - __bfloat162float(hx));
                    Clo[mrow * (size_t)ldc + n + 1] = __float2bfloat16(vy - __bfloat162float(hy));
                }
            }
        }
    }
}

// ============== recurrence GEMM: single fp16 term, K-chunk 64 ==================
// gh[B,4H] = fp16(h) @ fp16(Whh)^T. Full 128B smem rows = 64 fp16 K-elements.
// Same 3-stage pipeline (prefetch-first order, R9-proven), 3 CTAs/SM, 16 syncs.
#define HCHUNK 64

__global__ __launch_bounds__(128, 3)
void mma_gemm_h1(const __half* __restrict__ A, const __half* __restrict__ B,
                 float* __restrict__ C, int K, int ldc) {
    extern __shared__ char sm[];
    const uint32_t base = (smem_u32(sm) + 1023u) & ~1023u;
    const int tid = threadIdx.x;
    const int wid = tid >> 5, lane = tid & 31;
    const int wn = wid * 32;

    const __half* A_b = A + (size_t)blockIdx.y * 64 * K;
    const __half* B_b = B + (size_t)blockIdx.x * 128 * K;

    const int nchunk = K / HCHUNK;      // 16

    float acc[4][4][4];
    #pragma unroll
    for (int mi = 0; mi < 4; mi++)
        #pragma unroll
        for (int nj = 0; nj < 4; nj++)
            #pragma unroll
            for (int q = 0; q < 4; q++) acc[mi][nj][q] = 0.f;

    auto prefetch = [&](int ch) {
        const int kc = ch * HCHUNK;
        const uint32_t st = base + (uint32_t)(ch % F_NSTAGE) * F_STAGE;
        // A: 64 rows x 8 x 16B (full 128B row = 64 fp16)
        #pragma unroll
        for (int it = 0; it < 4; it++) {
            const int idx = it * 128 + tid;        // 0..511
            const int row = idx >> 3;
            const int g   = idx & 7;
            const uint32_t off = SMEM_SWIZZLE_128B((uint32_t)(row * 128 + g * 16));
            cp_async16(st + off, A_b + (size_t)row * K + kc + g * 8);
        }
        // B: 128 rows x 8 x 16B
        #pragma unroll
        for (int it = 0; it < 8; it++) {
            const int idx = it * 128 + tid;        // 0..1023
            const int row = idx >> 3;
            const int g   = idx & 7;
            const uint32_t off = SMEM_SWIZZLE_128B((uint32_t)(row * 128 + g * 16));
            cp_async16(st + A_TILE + off, B_b + (size_t)row * K + kc + g * 8);
        }
    };

    prefetch(0); CP_COMMIT();
    prefetch(1); CP_COMMIT();

    const int tsel = lane >> 3, rin = lane & 7;

    for (int ch = 0; ch < nchunk; ch++) {
        if (ch + 2 < nchunk) {
            prefetch(ch + 2);
            CP_COMMIT();
            CP_WAIT(2);
        } else {
            CP_WAIT(0);
        }
        __syncthreads();

        const uint32_t st = base + (uint32_t)(ch % F_NSTAGE) * F_STAGE;
        const uint32_t sB = st + A_TILE;

        #pragma unroll
        for (int kk = 0; kk < HCHUNK; kk += 16) {
            const int colb = (kk + (tsel >> 1) * 8) * 2;   // 0..127 bytes
            uint32_t a[4][4];
            #pragma unroll
            for (int mi = 0; mi < 4; mi++) {
                const int row = mi * 16 + (tsel & 1) * 8 + rin;
                ldsm_x4(st + SMEM_SWIZZLE_128B((uint32_t)(row * 128 + colb)),
                        a[mi][0], a[mi][1], a[mi][2], a[mi][3]);
            }
            uint32_t b[4][2];
            #pragma unroll
            for (int g = 0; g < 2; g++) {
                const int row = wn + g * 16 + (tsel & 1) * 8 + rin;
                uint32_t r0, r1, r2, r3;
                ldsm_x4(sB + SMEM_SWIZZLE_128B((uint32_t)(row * 128 + colb)),
                        r0, r1, r2, r3);
                b[g * 2 + 0][0] = r0; b[g * 2 + 0][1] = r2;
                b[g * 2 + 1][0] = r1; b[g * 2 + 1][1] = r3;
            }
            #pragma unroll
            for (int mi = 0; mi < 4; mi++)
                #pragma unroll
                for (int nj = 0; nj < 4; nj++)
                    mma_f16(acc[mi][nj], a[mi], b[nj]);
        }
        __syncthreads();
    }

    // epilogue (no bias, float C)
    const int r0 = lane >> 2;
    const int c0 = (lane & 3) * 2;
    #pragma unroll
    for (int mi = 0; mi < 4; mi++) {
        const size_t m0 = (size_t)blockIdx.y * 64 + mi * 16;
        #pragma unroll
        for (int nj = 0; nj < 4; nj++) {
            const int n = blockIdx.x * 128 + wn + nj * 8 + c0;
            *(float2*)(C + (m0 + r0) * (size_t)ldc + n) =
                make_float2(acc[mi][nj][0], acc[mi][nj][1]);
            *(float2*)(C + (m0 + r0 + 8) * (size_t)ldc + n) =
                make_float2(acc[mi][nj][2], acc[mi][nj][3]);
        }
    }
}

// ---------------- LSTM cell elementwise (libm; h -> single fp16) ----------------
__global__ void lstm_cell_kernel(const float* __restrict__ gx, float* __restrict__ out_t) {
    int idx = blockIdx.x * blockDim.x + threadIdx.x;
    if (idx >= BH) return;
    int b = idx / HH, hh = idx % HH;
    size_t base = (size_t)b * GG;
    float gi = gx[base + hh]          + g_gh[base + hh];
    float gf = gx[base + HH + hh]     + g_gh[base + HH + hh];
    float gg = gx[base + 2 * HH + hh] + g_gh[base + 2 * HH + hh];
    float go = gx[base + 3 * HH + hh] + g_gh[base + 3 * HH + hh];
    float i = 1.f / (1.f + expf(-gi));
    float f = 1.f / (1.f + expf(-gf));
    float g = tanhf(gg);
    float o = 1.f / (1.f + expf(-go));
    float cn = f * g_c[idx] + i * g;
    float hn = o * tanhf(cn);
    g_c[idx] = cn;
    g_hf[idx] = __float2half(hn);
    out_t[idx] = hn;
}

__global__ void copy_hc_kernel(const float* __restrict__ last_h, float* __restrict__ dst) {
    int i = blockIdx.x * blockDim.x + threadIdx.x;
    if (i < BH) { dst[i] = last_h[i]; dst[BH + i] = g_c[i]; }
}

// ---------------- launch ----------------
extern "C" void kernel_launch(void* const* d_in, const int* in_sizes, int n_in,
                              void* d_out, int out_size) {
    const float* inputs = (const float*)d_in[0];
    const float* h0     = (const float*)d_in[1];
    const float* c0     = (const float*)d_in[2];
    const float* W_emb  = (const float*)d_in[3];
    const float* b_emb  = (const float*)d_in[4];
    const float* W_ih   = (const float*)d_in[5];
    const float* W_hh   = (const float*)d_in[6];
    const float* b_ih   = (const float*)d_in[7];
    const float* b_hh   = (const float*)d_in[8];
    float* out = (float*)d_out;

    // Real device addresses of scratch globals (host-shadow trap otherwise).
    float *p_gx, *p_gh, *p_biasc;
    bf16 *p_xhi, *p_xlo, *p_wTh, *p_wTl, *p_wch, *p_wcl;
    bf16 *p_wihh, *p_wihl;
    __half *p_hf, *p_whh;
    cudaGetSymbolAddress((void**)&p_xhi,  g_xhi);
    cudaGetSymbolAddress((void**)&p_xlo,  g_xlo);
    cudaGetSymbolAddress((void**)&p_wTh,  g_wembT_hi);
    cudaGetSymbolAddress((void**)&p_wTl,  g_wembT_lo);
    cudaGetSymbolAddress((void**)&p_wch,  g_wc_hi);
    cudaGetSymbolAddress((void**)&p_wcl,  g_wc_lo);
    cudaGetSymbolAddress((void**)&p_biasc,g_bias_c);
    cudaGetSymbolAddress((void**)&p_gx,   g_gx);
    cudaGetSymbolAddress((void**)&p_gh,   g_gh);
    cudaGetSymbolAddress((void**)&p_hf,   g_hf);
    cudaGetSymbolAddress((void**)&p_wihh, g_wih_hi);
    cudaGetSymbolAddress((void**)&p_wihl, g_wih_lo);
    cudaGetSymbolAddress((void**)&p_whh,  g_whh);

    cudaFuncSetAttribute(mma_gemm_f<0>,
                         cudaFuncAttributeMaxDynamicSharedMemorySize, SMEM_F_BYTES);
    cudaFuncSetAttribute(mma_gemm_f<1>,
                         cudaFuncAttributeMaxDynamicSharedMemorySize, SMEM_F_BYTES);
    cudaFuncSetAttribute(mma_gemm_h1,
                         cudaFuncAttributeMaxDynamicSharedMemorySize, SMEM_F_BYTES);

    // prep
    reorder_pad_kernel<<<(M1 * KPAD + 255) / 256, 256>>>(inputs);
    transpose_wemb_kernel<<<(KPAD * HH + 255) / 256, 256>>>(W_emb);
    state_init_kernel<<<(BH + 255) / 256, 256>>>(h0, c0);
    decomp_bf16_kernel<<<(GG * HH + 255) / 256, 256>>>(W_ih, p_wihh, p_wihl, GG * HH);
    conv_f16_kernel<<<(GG * HH + 255) / 256, 256>>>(W_hh, p_whh, GG * HH);
    bias_c_kernel<<<GG, 128>>>(W_ih, b_emb, b_ih, b_hh);

    // Wc = W_ih @ W_emb -> bf16 hi/lo [4096,128]
    mma_gemm_f<1><<<dim3(KPAD / 128, GG / 64), 128, SMEM_F_BYTES>>>(
        p_wihh, p_wihl, p_wTh, p_wTl, nullptr, nullptr, p_wch, p_wcl, HH, KPAD);

    // gx = x @ Wc^T + bias_c : [51200,128] @ [4096,128]^T -> [51200,4096]
    mma_gemm_f<0><<<dim3(GG / 128, M1 / 64), 128, SMEM_F_BYTES>>>(
        p_xhi, p_xlo, p_wch, p_wcl, p_biasc, p_gx, nullptr, nullptr, KPAD, GG);

    // recurrence: single-term fp16 GEMM + cell per step
    for (int t = 0; t < AA; t++) {
        mma_gemm_h1<<<dim3(GG / 128, BB / 64), 128, SMEM_F_BYTES>>>(
            p_hf, p_whh, p_gh, HH, GG);
        lstm_cell_kernel<<<(BH + 255) / 256, 256>>>(
            p_gx + (size_t)t * BB * GG, out + (size_t)t * BH);
    }

    // final (h, c) after output — only if the harness buffer includes them
    if (out_size >= (AA + 2) * BH) {
        copy_hc_kernel<<<(BH + 255) / 256, 256>>>(out + (size_t)(AA - 1) * BH,
                                                  out + (size_t)AA * BH);
    }
}

// round 15
// speedup vs baseline: 2.2804x; 1.1180x over previous
#include <cuda_runtime.h>
#include <cuda_fp16.h>
#include <cstdint>
#include <cstddef>

// Problem constants
#define BB   512
#define AA   100
#define HH   1024
#define INN  77          // S*T = 7*11
#define KPAD 128         // padded input-feature dim
#define GG   4096        // 4*H
#define M1   (AA*BB)     // 51200
#define BH   (BB*HH)     // 524288

// ---------------- scratch (device globals; no allocation allowed) ----------------
__device__ __half g_xh    [(size_t)M1 * KPAD];   // reordered+padded inputs (fp16)
__device__ __half g_wembT [(size_t)KPAD * HH];   // W_emb^T padded (fp16)
__device__ __half g_wih_h [(size_t)GG * HH];     // W_ih fp16 (for Wc GEMM)
__device__ __half g_wc    [(size_t)GG * KPAD];   // Wc = W_ih @ W_emb  (fp16)
__device__ float  g_bias_c[GG];                  // W_ih@b_emb + b_ih + b_hh (fp32)
__device__ __half g_gx    [(size_t)M1 * GG];     // precomputed input gates (fp16)
__device__ __half g_gh    [(size_t)BB * GG];     // recurrent gates (fp16)
__device__ __half g_hf    [BH];                  // h state (fp16)
__device__ float  g_c     [BH];                  // c state (fp32)
__device__ __half g_whh   [(size_t)GG * HH];     // Whh fp16

// ================= PTX helpers (sm_80+ standard; NO arch-'a' features) =========
__device__ __forceinline__ uint32_t smem_u32(const void* p) {
    uint32_t a;
    asm("{ .reg .u64 t; cvta.to.shared.u64 t, %1; cvt.u32.u64 %0, t; }" : "=r"(a) : "l"(p));
    return a;
}
#define SMEM_SWIZZLE_128B(o) ((o) ^ (((o) >> 3) & 0x70))

__device__ __forceinline__ void cp_async16(uint32_t smem_addr, const void* gptr) {
    asm volatile("cp.async.cg.shared.global [%0], [%1], 16;"
                 :: "r"(smem_addr), "l"(gptr) : "memory");
}
#define CP_COMMIT() asm volatile("cp.async.commit_group;" ::: "memory")
#define CP_WAIT(n)  asm volatile("cp.async.wait_group %0;" :: "n"(n) : "memory")

__device__ __forceinline__ void ldsm_x4(uint32_t addr, uint32_t& r0, uint32_t& r1,
                                        uint32_t& r2, uint32_t& r3) {
    asm volatile("ldmatrix.sync.aligned.m8n8.x4.shared.b16 {%0,%1,%2,%3}, [%4];"
                 : "=r"(r0), "=r"(r1), "=r"(r2), "=r"(r3) : "r"(addr));
}

__device__ __forceinline__ void mma_f16(float* d, const uint32_t* a, const uint32_t* b) {
    asm volatile(
        "mma.sync.aligned.m16n8k16.row.col.f32.f16.f16.f32 "
        "{%0,%1,%2,%3}, {%4,%5,%6,%7}, {%8,%9}, {%0,%1,%2,%3};"
        : "+f"(d[0]), "+f"(d[1]), "+f"(d[2]), "+f"(d[3])
        : "r"(a[0]), "r"(a[1]), "r"(a[2]), "r"(a[3]), "r"(b[0]), "r"(b[1]));
}

// ================= prep kernels =================
__global__ void reorder_pad_kernel(const float* __restrict__ inputs) {
    int idx = blockIdx.x * blockDim.x + threadIdx.x;
    if (idx >= M1 * KPAD) return;
    int i = idx & (KPAD - 1);
    int r = idx >> 7;         // r = a*B + b
    int b = r % BB;
    int a = r / BB;
    float v = (i < INN) ? inputs[(size_t)b * (AA * INN) + (size_t)a * INN + i] : 0.f;
    g_xh[idx] = __float2half(v);
}

// W_emb [H,77] -> transposed+padded fp16 [128, H]
__global__ void transpose_wemb_kernel(const float* __restrict__ W_emb) {
    int idx = blockIdx.x * blockDim.x + threadIdx.x;
    if (idx >= KPAD * HH) return;
    int h = idx & (HH - 1);
    int n = idx >> 10;        // padded input-feature index
    float v = (n < INN) ? W_emb[(size_t)h * INN + n] : 0.f;
    g_wembT[idx] = __float2half(v);
}

// bias_c[j] = dot(W_ih[j,:], b_emb) + b_ih[j] + b_hh[j]; one 128-thr block per j
__global__ void bias_c_kernel(const float* __restrict__ W_ih, const float* __restrict__ b_emb,
                              const float* __restrict__ b_ih, const float* __restrict__ b_hh) {
    __shared__ float red[4];
    const int j = blockIdx.x;
    const int tid = threadIdx.x;
    float s = 0.f;
    for (int h = tid; h < HH; h += 128)
        s += W_ih[(size_t)j * HH + h] * b_emb[h];
    #pragma unroll
    for (int o = 16; o > 0; o >>= 1) s += __shfl_down_sync(0xFFFFFFFFu, s, o);
    if ((tid & 31) == 0) red[tid >> 5] = s;
    __syncthreads();
    if (tid == 0)
        g_bias_c[j] = red[0] + red[1] + red[2] + red[3] + b_ih[j] + b_hh[j];
}

__global__ void state_init_kernel(const float* __restrict__ h0, const float* __restrict__ c0) {
    int i = blockIdx.x * blockDim.x + threadIdx.x;
    if (i >= BH) return;
    g_hf[i] = __float2half(h0[i]);
    g_c[i] = c0[i];
}

__global__ void conv_f16_kernel(const float* __restrict__ src, __half* __restrict__ dst, int n) {
    int i = blockIdx.x * blockDim.x + threadIdx.x;
    if (i < n) dst[i] = __float2half(src[i]);
}

// ============== fp16 single-term GEMM, K-chunk 64 (R14-proven pipeline) ========
// C[M,N] = A @ B^T (+bias); fp32 accum, single fp16 MMA term. CTA tile 64x128,
// 4 warps (warp tile 64x32), full 128B smem rows = 64 fp16 K-elems.
// 3-stage cp.async (prefetch-first order), 3 CTAs/SM.
// EPI: 0 = float C, 1 = __half C. bias (fp32) added before store when non-null.
#define HCHUNK 64
#define A_TILE 8192                     // 64 rows * 128B
#define B_TILE 16384                    // 128 rows * 128B
#define F_STAGE (A_TILE + B_TILE)       // 24 KB
#define F_NSTAGE 3
#define SMEM_F_BYTES (F_NSTAGE * F_STAGE + 1024)

template<int EPI>
__global__ __launch_bounds__(128, 3)
void mma_gemm_h1(const __half* __restrict__ A, const __half* __restrict__ B,
                 const float* __restrict__ bias, void* __restrict__ Cv,
                 int K, int ldc) {
    extern __shared__ char sm[];
    const uint32_t base = (smem_u32(sm) + 1023u) & ~1023u;
    const int tid = threadIdx.x;
    const int wid = tid >> 5, lane = tid & 31;
    const int wn = wid * 32;

    const __half* A_b = A + (size_t)blockIdx.y * 64 * K;
    const __half* B_b = B + (size_t)blockIdx.x * 128 * K;

    const int nchunk = K / HCHUNK;

    float acc[4][4][4];
    #pragma unroll
    for (int mi = 0; mi < 4; mi++)
        #pragma unroll
        for (int nj = 0; nj < 4; nj++)
            #pragma unroll
            for (int q = 0; q < 4; q++) acc[mi][nj][q] = 0.f;

    auto prefetch = [&](int ch) {
        const int kc = ch * HCHUNK;
        const uint32_t st = base + (uint32_t)(ch % F_NSTAGE) * F_STAGE;
        #pragma unroll
        for (int it = 0; it < 4; it++) {
            const int idx = it * 128 + tid;        // 0..511
            const int row = idx >> 3;
            const int g   = idx & 7;
            const uint32_t off = SMEM_SWIZZLE_128B((uint32_t)(row * 128 + g * 16));
            cp_async16(st + off, A_b + (size_t)row * K + kc + g * 8);
        }
        #pragma unroll
        for (int it = 0; it < 8; it++) {
            const int idx = it * 128 + tid;        // 0..1023
            const int row = idx >> 3;
            const int g   = idx & 7;
            const uint32_t off = SMEM_SWIZZLE_128B((uint32_t)(row * 128 + g * 16));
            cp_async16(st + A_TILE + off, B_b + (size_t)row * K + kc + g * 8);
        }
    };

    prefetch(0); CP_COMMIT();
    if (nchunk > 1) { prefetch(1); CP_COMMIT(); }

    const int tsel = lane >> 3, rin = lane & 7;

    for (int ch = 0; ch < nchunk; ch++) {
        if (ch + 2 < nchunk) {
            prefetch(ch + 2);
            CP_COMMIT();
            CP_WAIT(2);
        } else {
            CP_WAIT(0);
        }
        __syncthreads();

        const uint32_t st = base + (uint32_t)(ch % F_NSTAGE) * F_STAGE;
        const uint32_t sB = st + A_TILE;

        #pragma unroll
        for (int kk = 0; kk < HCHUNK; kk += 16) {
            const int colb = (kk + (tsel >> 1) * 8) * 2;   // 0..127 bytes
            uint32_t a[4][4];
            #pragma unroll
            for (int mi = 0; mi < 4; mi++) {
                const int row = mi * 16 + (tsel & 1) * 8 + rin;
                ldsm_x4(st + SMEM_SWIZZLE_128B((uint32_t)(row * 128 + colb)),
                        a[mi][0], a[mi][1], a[mi][2], a[mi][3]);
            }
            uint32_t b[4][2];
            #pragma unroll
            for (int g = 0; g < 2; g++) {
                const int row = wn + g * 16 + (tsel & 1) * 8 + rin;
                uint32_t r0, r1, r2, r3;
                ldsm_x4(sB + SMEM_SWIZZLE_128B((uint32_t)(row * 128 + colb)),
                        r0, r1, r2, r3);
                b[g * 2 + 0][0] = r0; b[g * 2 + 0][1] = r2;
                b[g * 2 + 1][0] = r1; b[g * 2 + 1][1] = r3;
            }
            #pragma unroll
            for (int mi = 0; mi < 4; mi++)
                #pragma unroll
                for (int nj = 0; nj < 4; nj++)
                    mma_f16(acc[mi][nj], a[mi], b[nj]);
        }
        __syncthreads();
    }

    // ---------------- epilogue ----------------
    const int r0 = lane >> 2;
    const int c0 = (lane & 3) * 2;
    #pragma unroll
    for (int mi = 0; mi < 4; mi++) {
        const size_t m0 = (size_t)blockIdx.y * 64 + mi * 16;
        #pragma unroll
        for (int nj = 0; nj < 4; nj++) {
            const int n = blockIdx.x * 128 + wn + nj * 8 + c0;
            float bx = 0.f, by = 0.f;
            if (bias) { bx = bias[n]; by = bias[n + 1]; }
            float vs[4] = {acc[mi][nj][0] + bx, acc[mi][nj][1] + by,
                           acc[mi][nj][2] + bx, acc[mi][nj][3] + by};
            if (EPI == 0) {
                float* C = (float*)Cv;
                *(float2*)(C + (m0 + r0) * (size_t)ldc + n) = make_float2(vs[0], vs[1]);
                *(float2*)(C + (m0 + r0 + 8) * (size_t)ldc + n) = make_float2(vs[2], vs[3]);
            } else {
                __half* C = (__half*)Cv;
                *(__half2*)(C + (m0 + r0) * (size_t)ldc + n) =
                    __floats2half2_rn(vs[0], vs[1]);
                *(__half2*)(C + (m0 + r0 + 8) * (size_t)ldc + n) =
                    __floats2half2_rn(vs[2], vs[3]);
            }
        }
    }
}

// ---------------- LSTM cell elementwise (fp16 gates in, fp32 math) --------------
__global__ void lstm_cell_kernel(const __half* __restrict__ gx, float* __restrict__ out_t) {
    int idx = blockIdx.x * blockDim.x + threadIdx.x;
    if (idx >= BH) return;
    int b = idx / HH, hh = idx % HH;
    size_t base = (size_t)b * GG;
    float gi = __half2float(gx[base + hh])          + __half2float(g_gh[base + hh]);
    float gf = __half2float(gx[base + HH + hh])     + __half2float(g_gh[base + HH + hh]);
    float gg = __half2float(gx[base + 2 * HH + hh]) + __half2float(g_gh[base + 2 * HH + hh]);
    float go = __half2float(gx[base + 3 * HH + hh]) + __half2float(g_gh[base + 3 * HH + hh]);
    float i = 1.f / (1.f + expf(-gi));
    float f = 1.f / (1.f + expf(-gf));
    float g = tanhf(gg);
    float o = 1.f / (1.f + expf(-go));
    float cn = f * g_c[idx] + i * g;
    float hn = o * tanhf(cn);
    g_c[idx] = cn;
    g_hf[idx] = __float2half(hn);
    out_t[idx] = hn;
}

__global__ void copy_hc_kernel(const float* __restrict__ last_h, float* __restrict__ dst) {
    int i = blockIdx.x * blockDim.x + threadIdx.x;
    if (i < BH) { dst[i] = last_h[i]; dst[BH + i] = g_c[i]; }
}

// ---------------- launch ----------------
extern "C" void kernel_launch(void* const* d_in, const int* in_sizes, int n_in,
                              void* d_out, int out_size) {
    const float* inputs = (const float*)d_in[0];
    const float* h0     = (const float*)d_in[1];
    const float* c0     = (const float*)d_in[2];
    const float* W_emb  = (const float*)d_in[3];
    const float* b_emb  = (const float*)d_in[4];
    const float* W_ih   = (const float*)d_in[5];
    const float* W_hh   = (const float*)d_in[6];
    const float* b_ih   = (const float*)d_in[7];
    const float* b_hh   = (const float*)d_in[8];
    float* out = (float*)d_out;

    // Real device addresses of scratch globals (host-shadow trap otherwise).
    float *p_biasc;
    __half *p_xh, *p_wembT, *p_wih, *p_wc, *p_gx, *p_gh, *p_hf, *p_whh;
    cudaGetSymbolAddress((void**)&p_xh,    g_xh);
    cudaGetSymbolAddress((void**)&p_wembT, g_wembT);
    cudaGetSymbolAddress((void**)&p_wih,   g_wih_h);
    cudaGetSymbolAddress((void**)&p_wc,    g_wc);
    cudaGetSymbolAddress((void**)&p_biasc, g_bias_c);
    cudaGetSymbolAddress((void**)&p_gx,    g_gx);
    cudaGetSymbolAddress((void**)&p_gh,    g_gh);
    cudaGetSymbolAddress((void**)&p_hf,    g_hf);
    cudaGetSymbolAddress((void**)&p_whh,   g_whh);

    cudaFuncSetAttribute(mma_gemm_h1<0>,
                         cudaFuncAttributeMaxDynamicSharedMemorySize, SMEM_F_BYTES);
    cudaFuncSetAttribute(mma_gemm_h1<1>,
                         cudaFuncAttributeMaxDynamicSharedMemorySize, SMEM_F_BYTES);

    // prep
    reorder_pad_kernel<<<(M1 * KPAD + 255) / 256, 256>>>(inputs);
    transpose_wemb_kernel<<<(KPAD * HH + 255) / 256, 256>>>(W_emb);
    state_init_kernel<<<(BH + 255) / 256, 256>>>(h0, c0);
    conv_f16_kernel<<<(GG * HH + 255) / 256, 256>>>(W_ih, p_wih, GG * HH);
    conv_f16_kernel<<<(GG * HH + 255) / 256, 256>>>(W_hh, p_whh, GG * HH);
    bias_c_kernel<<<GG, 128>>>(W_ih, b_emb, b_ih, b_hh);

    // Wc = W_ih @ W_emb -> fp16 [4096, 128]
    mma_gemm_h1<1><<<dim3(KPAD / 128, GG / 64), 128, SMEM_F_BYTES>>>(
        p_wih, p_wembT, nullptr, p_wc, HH, KPAD);

    // gx = x @ Wc^T + bias_c : [51200,128] @ [4096,128]^T -> fp16 [51200,4096]
    mma_gemm_h1<1><<<dim3(GG / 128, M1 / 64), 128, SMEM_F_BYTES>>>(
        p_xh, p_wc, p_biasc, p_gx, KPAD, GG);

    // recurrence: single-term fp16 GEMM (gh fp16) + cell per step
    for (int t = 0; t < AA; t++) {
        mma_gemm_h1<1><<<dim3(GG / 128, BB / 64), 128, SMEM_F_BYTES>>>(
            p_hf, p_whh, nullptr, p_gh, HH, GG);
        lstm_cell_kernel<<<(BH + 255) / 256, 256>>>(
            p_gx + (size_t)t * BB * GG, out + (size_t)t * BH);
    }

    // final (h, c) after output — only if the harness buffer includes them
    if (out_size >= (AA + 2) * BH) {
        copy_hc_kernel<<<(BH + 255) / 256, 256>>>(out + (size_t)(AA - 1) * BH,
                                                  out + (size_t)AA * BH);
    }
}